// round 15
// baseline (speedup 1.0000x reference)
#include <cuda_runtime.h>
#include <cuda_fp16.h>
#include <cstdint>
#include <cstddef>

// Problem constants
#define BB 4
#define NN 512
#define MM 8192
#define QDIM 512
#define IDIM 256
#define HEADS 8
#define DHEAD 64
#define ADIM 512          // HEADS*DHEAD
#define KVC 1024          // 2*ADIM

// fp16 intermediates (device globals: allocation-guard-safe)
__device__ __half g_KV[(size_t)BB * MM * KVC];   // [b*M+m][0:512]=K, [512:1024]=V
__device__ __half g_Q [(size_t)BB * NN * ADIM];
__device__ __half g_O [(size_t)BB * NN * ADIM];

// ---------------------------------------------------------------------------
// helpers (base ISA, sm_80+)
// ---------------------------------------------------------------------------
__device__ __forceinline__ uint32_t pack2(float lo, float hi) {
    __half2 h = __floats2half2_rn(lo, hi);
    return *reinterpret_cast<uint32_t*>(&h);
}
// 2^x on both fp16 halves; volatile to pin placement for pipe interleaving
__device__ __forceinline__ uint32_t hex2(uint32_t x) {
    uint32_t r; asm volatile("ex2.approx.f16x2 %0, %1;" : "=r"(r) : "r"(x)); return r;
}
__device__ __forceinline__ __half2 u2h(uint32_t x) {
    return *reinterpret_cast<__half2*>(&x);
}
// D += A@B, m16n8k16 f16 inputs, f32 accum
__device__ __forceinline__ void mma16(float c[4], const uint32_t a[4],
                                      uint32_t b0, uint32_t b1) {
    asm volatile(
        "mma.sync.aligned.m16n8k16.row.col.f32.f16.f16.f32 "
        "{%0,%1,%2,%3}, {%4,%5,%6,%7}, {%8,%9}, {%0,%1,%2,%3};"
        : "+f"(c[0]), "+f"(c[1]), "+f"(c[2]), "+f"(c[3])
        : "r"(a[0]), "r"(a[1]), "r"(a[2]), "r"(a[3]), "r"(b0), "r"(b1));
}
__device__ __forceinline__ void ldmx2t(uint32_t& r0, uint32_t& r1, const void* p) {
    uint32_t ad = (uint32_t)__cvta_generic_to_shared(p);
    asm volatile("ldmatrix.sync.aligned.m8n8.x2.trans.shared.b16 {%0,%1}, [%2];"
                 : "=r"(r0), "=r"(r1) : "r"(ad));
}
__device__ __forceinline__ void ldmx4(uint32_t& r0, uint32_t& r1,
                                      uint32_t& r2, uint32_t& r3, const void* p) {
    uint32_t ad = (uint32_t)__cvta_generic_to_shared(p);
    asm volatile("ldmatrix.sync.aligned.m8n8.x4.shared.b16 {%0,%1,%2,%3}, [%4];"
                 : "=r"(r0), "=r"(r1), "=r"(r2), "=r"(r3) : "r"(ad));
}
__device__ __forceinline__ void cpa16(void* d, const void* s) {
    uint32_t ad = (uint32_t)__cvta_generic_to_shared(d);
    asm volatile("cp.async.cg.shared.global [%0], [%1], 16;" :: "r"(ad), "l"(s) : "memory");
}
#define CP_COMMIT() asm volatile("cp.async.commit_group;" ::: "memory")

// ===========================================================================
// fp16 tensor-core GEMM with register-stage pipelining (unchanged from R8).
// ===========================================================================
#define PAH 40   // A smem pitch (halves), conflict-free frag reads

template<int BN, bool AH, bool CH>
__device__ __forceinline__ void gemm_tc(const void* __restrict__ Av,
                                        const float* __restrict__ B,
                                        void* __restrict__ Cv,
                                        int M, int N, int K,
                                        const float* __restrict__ bo)
{
    constexpr int PBH = BN + 8;
    constexpr int NT  = BN / 32;

    __shared__ __half As[128 * PAH];
    __shared__ __half Bs[32 * PBH];

    const int tid = threadIdx.x;
    const int w   = tid >> 5, ln = tid & 31;
    const int gid = ln >> 2,  q  = ln & 3;
    const int wm  = w & 1,    wn = w >> 1;
    const int row0 = blockIdx.y * 128;
    const int col0 = blockIdx.x * BN;
    const uint32_t* As32 = reinterpret_cast<const uint32_t*>(As);

    float c[4][NT][4] = {};
    float4 la[4]; uint4 lah[2]; float4 lb[NT];

    auto ldAB = [&](int k0) {
        if (AH) {
            const __half* A = (const __half*)Av;
            #pragma unroll
            for (int u = 0; u < 2; u++) {
                int idx = u * 256 + tid;
                int r = idx >> 2, f = idx & 3;
                lah[u] = *reinterpret_cast<const uint4*>(
                    &A[(size_t)(row0 + r) * K + k0 + f * 8]);
            }
        } else {
            const float* A = (const float*)Av;
            #pragma unroll
            for (int u = 0; u < 4; u++) {
                int idx = u * 256 + tid;
                int r = idx >> 3, f = idx & 7;
                la[u] = *reinterpret_cast<const float4*>(
                    &A[(size_t)(row0 + r) * K + k0 + f * 4]);
            }
        }
        #pragma unroll
        for (int u = 0; u < NT; u++) {
            int idx = u * 256 + tid;
            int r = idx / (BN / 4), f = idx % (BN / 4);
            lb[u] = *reinterpret_cast<const float4*>(
                &B[(size_t)(k0 + r) * N + col0 + f * 4]);
        }
    };
    auto stAB = [&]() {
        if (AH) {
            #pragma unroll
            for (int u = 0; u < 2; u++) {
                int idx = u * 256 + tid;
                int r = idx >> 2, f = idx & 3;
                *reinterpret_cast<uint4*>(&As[r * PAH + f * 8]) = lah[u];
            }
        } else {
            #pragma unroll
            for (int u = 0; u < 4; u++) {
                int idx = u * 256 + tid;
                int r = idx >> 3, f = idx & 7;
                uint2 t = make_uint2(pack2(la[u].x, la[u].y), pack2(la[u].z, la[u].w));
                *reinterpret_cast<uint2*>(&As[r * PAH + f * 4]) = t;
            }
        }
        #pragma unroll
        for (int u = 0; u < NT; u++) {
            int idx = u * 256 + tid;
            int r = idx / (BN / 4), f = idx % (BN / 4);
            uint2 t = make_uint2(pack2(lb[u].x, lb[u].y), pack2(lb[u].z, lb[u].w));
            *reinterpret_cast<uint2*>(&Bs[r * PBH + f * 4]) = t;
        }
    };

    ldAB(0);
    for (int k0 = 0; k0 < K; k0 += 32) {
        stAB();
        __syncthreads();
        if (k0 + 32 < K) ldAB(k0 + 32);

        #pragma unroll
        for (int s = 0; s < 2; s++) {
            uint32_t a[4][4];
            #pragma unroll
            for (int mt = 0; mt < 4; mt++) {
                int w0 = (wm * 64 + mt * 16 + gid) * (PAH / 2) + s * 8 + q;
                a[mt][0] = As32[w0];
                a[mt][1] = As32[w0 + 8 * (PAH / 2)];
                a[mt][2] = As32[w0 + 4];
                a[mt][3] = As32[w0 + 8 * (PAH / 2) + 4];
            }
            uint32_t bf[NT][2];
            #pragma unroll
            for (int nt = 0; nt < NT; nt++) {
                int rowk = s * 16 + (ln & 15);
                int cb = wn * (BN / 4) + nt * 8;
                ldmx2t(bf[nt][0], bf[nt][1], &Bs[rowk * PBH + cb]);
            }
            #pragma unroll
            for (int mt = 0; mt < 4; mt++)
                #pragma unroll
                for (int nt = 0; nt < NT; nt++)
                    mma16(c[mt][nt], a[mt], bf[nt][0], bf[nt][1]);
        }
        __syncthreads();
    }

    #pragma unroll
    for (int mt = 0; mt < 4; mt++) {
        int r0 = row0 + wm * 64 + mt * 16 + gid;
        #pragma unroll
        for (int nt = 0; nt < NT; nt++) {
            int cc = col0 + wn * (BN / 4) + nt * 8 + 2 * q;
            if (CH) {
                __half* C = (__half*)Cv;
                *reinterpret_cast<__half2*>(&C[(size_t)r0 * N + cc]) =
                    __floats2half2_rn(c[mt][nt][0], c[mt][nt][1]);
                *reinterpret_cast<__half2*>(&C[(size_t)(r0 + 8) * N + cc]) =
                    __floats2half2_rn(c[mt][nt][2], c[mt][nt][3]);
            } else {
                float* C = (float*)Cv;
                float b0 = bo ? bo[cc]     : 0.f;
                float b1 = bo ? bo[cc + 1] : 0.f;
                *reinterpret_cast<float2*>(&C[(size_t)r0 * N + cc]) =
                    make_float2(c[mt][nt][0] + b0, c[mt][nt][1] + b1);
                *reinterpret_cast<float2*>(&C[(size_t)(r0 + 8) * N + cc]) =
                    make_float2(c[mt][nt][2] + b0, c[mt][nt][3] + b1);
            }
        }
    }
}

__global__ __launch_bounds__(256) void kv_kernel(const float* __restrict__ context,
                                                 const float* __restrict__ Wkv) {
    gemm_tc<128, false, true>(context, Wkv, g_KV, BB * MM, KVC, IDIM, nullptr);
}
__global__ __launch_bounds__(256) void q_kernel(const float* __restrict__ x,
                                                const float* __restrict__ Wq) {
    gemm_tc<64, false, true>(x, Wq, g_Q, BB * NN, ADIM, QDIM, nullptr);
}
__global__ __launch_bounds__(256) void out_kernel(const float* __restrict__ Wo,
                                                  const float* __restrict__ bo,
                                                  float* __restrict__ out) {
    gemm_tc<64, true, false>(g_O, Wo, out, BB * NN, QDIM, ADIM, bo);
}

// Empty kernel: shifts attn_kernel into the profiled (4th) launch slot.
__global__ void dummy_kernel() {}

// ===========================================================================
// fp16 flash attention (128 q-rows, 4 q-groups x 2 kv-halves), 128-row KV
// chunks, ONE sync per chunk. K and V b-fragments register-double-buffered
// (loads issued one step ahead of consuming mma). exp via f16x2 MUFU
// interleaved with PV mma stream; l via hadd2-tree + quad shuffles.
// grid (NN/128, HEADS, BB), 256 threads.
// ===========================================================================
#define AKP 72   // K/V smem pitch (halves); 144B ≡ 16 mod 128

__global__ __launch_bounds__(256, 1) void attn_kernel()
{
    // 2 buffers x (K 128xAKP + V 128xAKP) halves = 73728 B total
    __shared__ __align__(16) char sbuf[73728];
    __half (*Ks)[128 * AKP] = reinterpret_cast<__half(*)[128 * AKP]>(sbuf);
    __half (*Vs)[128 * AKP] = reinterpret_cast<__half(*)[128 * AKP]>(sbuf + 36864);

    const int b  = blockIdx.z;
    const int h  = blockIdx.y;
    const int n0 = blockIdx.x * 128;
    const int tid = threadIdx.x;
    const int w   = tid >> 5, ln = tid & 31;
    const int gid = ln >> 2,  q  = ln & 3;
    const int qg  = w & 3;     // q-group: rows 32*qg .. +32
    const int kh  = w >> 2;    // kv half within a 64-row half-chunk

    // ldmatrix.x4 lane mapping for K b-frags
    const int lmL   = ln & 7;
    const int lmSel = ln >> 3;
    const int lmRow = ((lmSel >> 1) << 3) + lmL;     // nt-pair-local row 0..15
    const int lmKof = (lmSel & 1) << 3;              // k offset 0/8 halves

    // Q fragments: 32 rows x 64 k per warp; fold 0.125*log2(e) into Q
    const __half2 LSC2 = __float2half2_rn(0.1803368801f);
    uint32_t qa[4][2][4];
    {
        const __half* Qg = g_Q + ((size_t)(b * NN + n0 + qg * 32)) * ADIM + h * DHEAD;
        #pragma unroll
        for (int kt = 0; kt < 4; kt++)
            #pragma unroll
            for (int mt = 0; mt < 2; mt++) {
                const __half* r0 = Qg + (size_t)(mt * 16 + gid) * ADIM + kt * 16 + 2 * q;
                const __half* r8 = r0 + 8 * ADIM;
                __half2 v0 = __hmul2(*reinterpret_cast<const __half2*>(r0),     LSC2);
                __half2 v1 = __hmul2(*reinterpret_cast<const __half2*>(r8),     LSC2);
                __half2 v2 = __hmul2(*reinterpret_cast<const __half2*>(r0 + 8), LSC2);
                __half2 v3 = __hmul2(*reinterpret_cast<const __half2*>(r8 + 8), LSC2);
                qa[kt][mt][0] = *reinterpret_cast<uint32_t*>(&v0);
                qa[kt][mt][1] = *reinterpret_cast<uint32_t*>(&v1);
                qa[kt][mt][2] = *reinterpret_cast<uint32_t*>(&v2);
                qa[kt][mt][3] = *reinterpret_cast<uint32_t*>(&v3);
            }
    }

    float oc[2][8][4] = {};
    float ls[2][2] = {};    // row sums l: [mt][row gid / gid+8]
    const __half* KVb = g_KV + (size_t)b * MM * KVC + h * DHEAD;

    // 128-row chunk loader: 8 x 16B cp.async per thread (K 64 cols + V 64 cols)
    auto load_chunk = [&](int m0, int bi) {
        #pragma unroll
        for (int u = 0; u < 8; u++) {
            int idx = u * 256 + tid;
            int tile = idx >> 10, r = (idx >> 3) & 127, f = idx & 7;
            const __half* src = KVb + (size_t)(m0 + r) * KVC + tile * ADIM + f * 8;
            __half* dst = (tile ? Vs[bi] : Ks[bi]) + r * AKP + f * 8;
            cpa16(dst, src);
        }
        CP_COMMIT();
    };

    load_chunk(0, 0);
    int buf = 0;

    for (int c = 0; c < MM / 128; c++) {
        asm volatile("cp.async.wait_group 0;" ::: "memory");
        __syncthreads();   // chunk c ready for all; all reads of buf^1 finished
        if (c + 1 < MM / 128) load_chunk((c + 1) * 128, buf ^ 1);

        #pragma unroll
        for (int hh = 0; hh < 2; hh++) {
            const int base = hh * 64 + kh * 32;   // this warp's 32 kv rows

            // --- S = Q @ K^T (log2 domain). K b-frags double-buffered in regs:
            //     ldmatrix.x4 for kt+1 issued before kt's mma block.
            float sc[2][4][4] = {};
            uint32_t kb[2][2][4];   // [parity][pp][frag]
            #pragma unroll
            for (int pp = 0; pp < 2; pp++)
                ldmx4(kb[0][pp][0], kb[0][pp][1], kb[0][pp][2], kb[0][pp][3],
                      &Ks[buf][(base + pp * 16 + lmRow) * AKP + lmKof]);
            #pragma unroll
            for (int kt = 0; kt < 4; kt++) {
                if (kt < 3) {
                    #pragma unroll
                    for (int pp = 0; pp < 2; pp++)
                        ldmx4(kb[(kt + 1) & 1][pp][0], kb[(kt + 1) & 1][pp][1],
                              kb[(kt + 1) & 1][pp][2], kb[(kt + 1) & 1][pp][3],
                              &Ks[buf][(base + pp * 16 + lmRow) * AKP + (kt + 1) * 16 + lmKof]);
                }
                #pragma unroll
                for (int pp = 0; pp < 2; pp++) {
                    mma16(sc[0][2*pp],   qa[kt][0], kb[kt & 1][pp][0], kb[kt & 1][pp][1]);
                    mma16(sc[1][2*pp],   qa[kt][1], kb[kt & 1][pp][0], kb[kt & 1][pp][1]);
                    mma16(sc[0][2*pp+1], qa[kt][0], kb[kt & 1][pp][2], kb[kt & 1][pp][3]);
                    mma16(sc[1][2*pp+1], qa[kt][1], kb[kt & 1][pp][2], kb[kt & 1][pp][3]);
                }
            }

            // --- pack s into f16x2 (a-frag layout)
            uint32_t sb[2][2][4];
            #pragma unroll
            for (int mt = 0; mt < 2; mt++)
                #pragma unroll
                for (int t = 0; t < 2; t++) {
                    sb[mt][t][0] = pack2(sc[mt][2*t][0],   sc[mt][2*t][1]);
                    sb[mt][t][1] = pack2(sc[mt][2*t][2],   sc[mt][2*t][3]);
                    sb[mt][t][2] = pack2(sc[mt][2*t+1][0], sc[mt][2*t+1][1]);
                    sb[mt][t][3] = pack2(sc[mt][2*t+1][2], sc[mt][2*t+1][3]);
                }

            // --- prefetch ALL V b-frags for t=0 before they're needed
            uint32_t vb0[8][2], vb1[8][2];
            {
                int rowk = base + (ln & 15);
                #pragma unroll
                for (int nt = 0; nt < 8; nt++)
                    ldmx2t(vb0[nt][0], vb0[nt][1], &Vs[buf][rowk * AKP + nt * 8]);
            }

            // --- p = 2^s for t=0 (8 MUFU f16x2 ops)
            uint32_t pa[2][2][4];
            #pragma unroll
            for (int i = 0; i < 4; i++) {
                pa[0][0][i] = hex2(sb[0][0][i]);
                pa[1][0][i] = hex2(sb[1][0][i]);
            }

            // --- PV t=0 (pre-loaded vb0); interleave t=1 V loads + t=1 exp
            {
                int rowk1 = base + 16 + (ln & 15);
                #pragma unroll
                for (int nt = 0; nt < 8; nt++) {
                    ldmx2t(vb1[nt][0], vb1[nt][1], &Vs[buf][rowk1 * AKP + nt * 8]);
                    if (nt < 4) pa[0][1][nt] = hex2(sb[0][1][nt]);
                    mma16(oc[0][nt], pa[0][0], vb0[nt][0], vb0[nt][1]);
                    if (nt >= 4) pa[1][1][nt - 4] = hex2(sb[1][1][nt - 4]);
                    mma16(oc[1][nt], pa[1][0], vb0[nt][0], vb0[nt][1]);
                }
            }
            // --- PV t=1 (pre-loaded vb1, no loads in loop)
            #pragma unroll
            for (int nt = 0; nt < 8; nt++) {
                mma16(oc[0][nt], pa[0][1], vb1[nt][0], vb1[nt][1]);
                mma16(oc[1][nt], pa[1][1], vb1[nt][0], vb1[nt][1]);
            }

            // --- l += rowsum(P) via hadd2 tree + quad shuffles (ALU pipe)
            #pragma unroll
            for (int mt = 0; mt < 2; mt++) {
                __half2 sA = __hadd2(__hadd2(u2h(pa[mt][0][0]), u2h(pa[mt][0][2])),
                                     __hadd2(u2h(pa[mt][1][0]), u2h(pa[mt][1][2])));
                float fA = __low2float(sA) + __high2float(sA);
                fA += __shfl_xor_sync(0xffffffffu, fA, 1);
                fA += __shfl_xor_sync(0xffffffffu, fA, 2);
                ls[mt][0] += fA;
                __half2 sB = __hadd2(__hadd2(u2h(pa[mt][0][1]), u2h(pa[mt][0][3])),
                                     __hadd2(u2h(pa[mt][1][1]), u2h(pa[mt][1][3])));
                float fB = __low2float(sB) + __high2float(sB);
                fB += __shfl_xor_sync(0xffffffffu, fB, 1);
                fB += __shfl_xor_sync(0xffffffffu, fB, 2);
                ls[mt][1] += fB;
            }
        }
        buf ^= 1;
    }

    // --- cross-half reduction (smem aliases KV buffers), normalize, store
    float* redO = reinterpret_cast<float*>(sbuf);            // [128][64]
    float* redL = reinterpret_cast<float*>(sbuf + 32768);    // [128]
    __syncthreads();
    if (kh == 1) {
        #pragma unroll
        for (int mt = 0; mt < 2; mt++) {
            int r0 = qg * 32 + mt * 16 + gid;
            #pragma unroll
            for (int nt = 0; nt < 8; nt++) {
                int cc = nt * 8 + 2 * q;
                redO[r0 * 64 + cc]           = oc[mt][nt][0];
                redO[r0 * 64 + cc + 1]       = oc[mt][nt][1];
                redO[(r0 + 8) * 64 + cc]     = oc[mt][nt][2];
                redO[(r0 + 8) * 64 + cc + 1] = oc[mt][nt][3];
            }
            if (q == 0) {
                redL[r0]     = ls[mt][0];
                redL[r0 + 8] = ls[mt][1];
            }
        }
    }
    __syncthreads();
    if (kh == 0) {
        #pragma unroll
        for (int mt = 0; mt < 2; mt++) {
            int r0 = qg * 32 + mt * 16 + gid;
            float inv0 = 1.f / (ls[mt][0] + redL[r0]);
            float inv8 = 1.f / (ls[mt][1] + redL[r0 + 8]);
            __half* Og0 = g_O + ((size_t)(b * NN + n0 + r0)) * ADIM + h * DHEAD;
            __half* Og8 = Og0 + 8 * ADIM;
            #pragma unroll
            for (int nt = 0; nt < 8; nt++) {
                int cc = nt * 8 + 2 * q;
                float s0 = (oc[mt][nt][0] + redO[r0 * 64 + cc])           * inv0;
                float s1 = (oc[mt][nt][1] + redO[r0 * 64 + cc + 1])       * inv0;
                float s2 = (oc[mt][nt][2] + redO[(r0 + 8) * 64 + cc])     * inv8;
                float s3 = (oc[mt][nt][3] + redO[(r0 + 8) * 64 + cc + 1]) * inv8;
                *reinterpret_cast<__half2*>(&Og0[cc]) = __floats2half2_rn(s0, s1);
                *reinterpret_cast<__half2*>(&Og8[cc]) = __floats2half2_rn(s2, s3);
            }
        }
    }
}

// ---------------------------------------------------------------------------
// Launch
// ---------------------------------------------------------------------------
extern "C" void kernel_launch(void* const* d_in, const int* in_sizes, int n_in,
                              void* d_out, int out_size)
{
    const float* x       = (const float*)d_in[0];
    const float* context = (const float*)d_in[1];
    const float* Wq      = (const float*)d_in[2];
    const float* Wkv     = (const float*)d_in[3];
    const float* Wo      = (const float*)d_in[4];
    const float* bo      = (const float*)d_in[5];
    float* out           = (float*)d_out;

    (void)in_sizes; (void)n_in; (void)out_size;

    dim3 blk(256);
    kv_kernel <<<dim3(KVC / 128,  (BB * MM) / 128), blk>>>(context, Wkv);
    q_kernel  <<<dim3(ADIM / 64,  (BB * NN) / 128), blk>>>(x, Wq);
    dummy_kernel<<<1, 32>>>();   // shifts attn into the profiled 4th slot
    attn_kernel<<<dim3(NN / 128, HEADS, BB), blk>>>();
    out_kernel<<<dim3(QDIM / 64,  (BB * NN) / 128), blk>>>(Wo, bo, out);
}

// round 16
// speedup vs baseline: 1.1680x; 1.1680x over previous
#include <cuda_runtime.h>
#include <cuda_fp16.h>
#include <cstdint>
#include <cstddef>

// Problem constants
#define BB 4
#define NN 512
#define MM 8192
#define QDIM 512
#define IDIM 256
#define HEADS 8
#define DHEAD 64
#define ADIM 512          // HEADS*DHEAD
#define KVC 1024          // 2*ADIM

// fp16 intermediates (device globals: allocation-guard-safe)
__device__ __half g_KV [(size_t)BB * MM * KVC];   // [b*M+m][0:512]=K, [512:1024]=V
__device__ __half g_Q  [(size_t)BB * NN * ADIM];
__device__ __half g_O  [(size_t)BB * NN * ADIM];
// fp16 pre-converted inputs
__device__ __half g_x  [(size_t)BB * NN * QDIM];
__device__ __half g_ctx[(size_t)BB * MM * IDIM];
__device__ __half g_Wq [(size_t)QDIM * ADIM];
__device__ __half g_Wkv[(size_t)IDIM * KVC];
__device__ __half g_Wo [(size_t)ADIM * QDIM];

// ---------------------------------------------------------------------------
// helpers (base ISA, sm_80+)
// ---------------------------------------------------------------------------
__device__ __forceinline__ uint32_t pack2(float lo, float hi) {
    __half2 h = __floats2half2_rn(lo, hi);
    return *reinterpret_cast<uint32_t*>(&h);
}
__device__ __forceinline__ uint32_t hex2(uint32_t x) {
    uint32_t r; asm volatile("ex2.approx.f16x2 %0, %1;" : "=r"(r) : "r"(x)); return r;
}
__device__ __forceinline__ __half2 u2h(uint32_t x) {
    return *reinterpret_cast<__half2*>(&x);
}
__device__ __forceinline__ void mma16(float c[4], const uint32_t a[4],
                                      uint32_t b0, uint32_t b1) {
    asm volatile(
        "mma.sync.aligned.m16n8k16.row.col.f32.f16.f16.f32 "
        "{%0,%1,%2,%3}, {%4,%5,%6,%7}, {%8,%9}, {%0,%1,%2,%3};"
        : "+f"(c[0]), "+f"(c[1]), "+f"(c[2]), "+f"(c[3])
        : "r"(a[0]), "r"(a[1]), "r"(a[2]), "r"(a[3]), "r"(b0), "r"(b1));
}
__device__ __forceinline__ void ldmx2t(uint32_t& r0, uint32_t& r1, const void* p) {
    uint32_t ad = (uint32_t)__cvta_generic_to_shared(p);
    asm volatile("ldmatrix.sync.aligned.m8n8.x2.trans.shared.b16 {%0,%1}, [%2];"
                 : "=r"(r0), "=r"(r1) : "r"(ad));
}
__device__ __forceinline__ void ldmx4(uint32_t& r0, uint32_t& r1,
                                      uint32_t& r2, uint32_t& r3, const void* p) {
    uint32_t ad = (uint32_t)__cvta_generic_to_shared(p);
    asm volatile("ldmatrix.sync.aligned.m8n8.x4.shared.b16 {%0,%1,%2,%3}, [%4];"
                 : "=r"(r0), "=r"(r1), "=r"(r2), "=r"(r3) : "r"(ad));
}
__device__ __forceinline__ void cpa16(void* d, const void* s) {
    uint32_t ad = (uint32_t)__cvta_generic_to_shared(d);
    asm volatile("cp.async.cg.shared.global [%0], [%1], 16;" :: "r"(ad), "l"(s) : "memory");
}
#define CP_COMMIT() asm volatile("cp.async.commit_group;" ::: "memory")
#define CP_WAIT0()  asm volatile("cp.async.wait_group 0;" ::: "memory")

// ===========================================================================
// One-shot fp32 -> fp16 conversion of all inputs (single kernel).
// Segments (float4 units): x 262144 | ctx 2097152 | Wq 65536 | Wkv 65536 | Wo 65536
// ===========================================================================
__global__ __launch_bounds__(256) void cvt_kernel(
    const float* __restrict__ x, const float* __restrict__ ctx,
    const float* __restrict__ Wq, const float* __restrict__ Wkv,
    const float* __restrict__ Wo)
{
    int i = blockIdx.x * 256 + threadIdx.x;
    const float* src; __half* dst; int off;
    if      (i < 262144)  { src = x;   dst = g_x;   off = i; }
    else if (i < 2359296) { src = ctx; dst = g_ctx; off = i - 262144; }
    else if (i < 2424832) { src = Wq;  dst = g_Wq;  off = i - 2359296; }
    else if (i < 2490368) { src = Wkv; dst = g_Wkv; off = i - 2424832; }
    else                  { src = Wo;  dst = g_Wo;  off = i - 2490368; }
    float4 v = reinterpret_cast<const float4*>(src)[off];
    uint2 t = make_uint2(pack2(v.x, v.y), pack2(v.z, v.w));
    *reinterpret_cast<uint2*>(&dst[(size_t)off * 4]) = t;
}

// ===========================================================================
// fp16 tensor-core GEMM, all-fp16 operands, cp.async double-buffered smem,
// ONE barrier per k-slab. C[M,N] = A[M,K] @ B[K,N] (+bias).
// CTA tile 128xBN, BK=32, 256 threads = 8 warps (2M x 4N).
// ===========================================================================
#define PAH 40   // A smem pitch (halves); 80B rows, 16B-aligned chunks

template<int BN, bool CH>
__device__ __forceinline__ void gemm_tc(const __half* __restrict__ A,
                                        const __half* __restrict__ B,
                                        void* __restrict__ Cv,
                                        int M, int N, int K,
                                        const float* __restrict__ bo)
{
    constexpr int PBH = BN + 8;    // 272B/144B rows, 16B-aligned chunks
    constexpr int NT  = BN / 32;

    __shared__ __half As[2][128 * PAH];
    __shared__ __half Bs[2][32 * PBH];

    const int tid = threadIdx.x;
    const int w   = tid >> 5, ln = tid & 31;
    const int gid = ln >> 2,  q  = ln & 3;
    const int wm  = w & 1,    wn = w >> 1;
    const int row0 = blockIdx.y * 128;
    const int col0 = blockIdx.x * BN;

    auto ldAB = [&](int k0, int st) {
        // A: 128 rows x 32 halves = 512 x 16B chunks (2 per thread)
        #pragma unroll
        for (int u = 0; u < 2; u++) {
            int idx = u * 256 + tid;
            int r = idx >> 2, f = idx & 3;
            cpa16(&As[st][r * PAH + f * 8], &A[(size_t)(row0 + r) * K + k0 + f * 8]);
        }
        // B: 32 rows x BN halves = 4*BN x 16B chunks
        #pragma unroll
        for (int u = 0; u < BN / 64; u++) {
            int idx = u * 256 + tid;
            int r = idx / (BN / 8), f = idx % (BN / 8);
            cpa16(&Bs[st][r * PBH + f * 8], &B[(size_t)(k0 + r) * N + col0 + f * 8]);
        }
        CP_COMMIT();
    };

    float c[4][NT][4] = {};

    ldAB(0, 0);
    int buf = 0;
    for (int k0 = 0; k0 < K; k0 += 32) {
        CP_WAIT0();
        __syncthreads();                    // slab ready; prior compute done
        if (k0 + 32 < K) ldAB(k0 + 32, buf ^ 1);

        const uint32_t* As32 = reinterpret_cast<const uint32_t*>(As[buf]);
        #pragma unroll
        for (int s = 0; s < 2; s++) {
            uint32_t a[4][4];
            #pragma unroll
            for (int mt = 0; mt < 4; mt++) {
                int w0 = (wm * 64 + mt * 16 + gid) * (PAH / 2) + s * 8 + q;
                a[mt][0] = As32[w0];
                a[mt][1] = As32[w0 + 8 * (PAH / 2)];
                a[mt][2] = As32[w0 + 4];
                a[mt][3] = As32[w0 + 8 * (PAH / 2) + 4];
            }
            uint32_t bf[NT][2];
            #pragma unroll
            for (int nt = 0; nt < NT; nt++) {
                int rowk = s * 16 + (ln & 15);
                int cb = wn * (BN / 4) + nt * 8;
                ldmx2t(bf[nt][0], bf[nt][1], &Bs[buf][rowk * PBH + cb]);
            }
            #pragma unroll
            for (int mt = 0; mt < 4; mt++)
                #pragma unroll
                for (int nt = 0; nt < NT; nt++)
                    mma16(c[mt][nt], a[mt], bf[nt][0], bf[nt][1]);
        }
        buf ^= 1;
    }

    #pragma unroll
    for (int mt = 0; mt < 4; mt++) {
        int r0 = row0 + wm * 64 + mt * 16 + gid;
        #pragma unroll
        for (int nt = 0; nt < NT; nt++) {
            int cc = col0 + wn * (BN / 4) + nt * 8 + 2 * q;
            if (CH) {
                __half* C = (__half*)Cv;
                *reinterpret_cast<__half2*>(&C[(size_t)r0 * N + cc]) =
                    __floats2half2_rn(c[mt][nt][0], c[mt][nt][1]);
                *reinterpret_cast<__half2*>(&C[(size_t)(r0 + 8) * N + cc]) =
                    __floats2half2_rn(c[mt][nt][2], c[mt][nt][3]);
            } else {
                float* C = (float*)Cv;
                float b0 = bo ? bo[cc]     : 0.f;
                float b1 = bo ? bo[cc + 1] : 0.f;
                *reinterpret_cast<float2*>(&C[(size_t)r0 * N + cc]) =
                    make_float2(c[mt][nt][0] + b0, c[mt][nt][1] + b1);
                *reinterpret_cast<float2*>(&C[(size_t)(r0 + 8) * N + cc]) =
                    make_float2(c[mt][nt][2] + b0, c[mt][nt][3] + b1);
            }
        }
    }
}

__global__ __launch_bounds__(256) void kv_kernel() {
    gemm_tc<128, true>(g_ctx, g_Wkv, g_KV, BB * MM, KVC, IDIM, nullptr);
}
__global__ __launch_bounds__(256) void q_kernel() {
    gemm_tc<64, true>(g_x, g_Wq, g_Q, BB * NN, ADIM, QDIM, nullptr);
}
__global__ __launch_bounds__(256) void out_kernel(const float* __restrict__ bo,
                                                  float* __restrict__ out) {
    gemm_tc<64, false>(g_O, g_Wo, out, BB * NN, QDIM, ADIM, bo);
}

// ===========================================================================
// fp16 flash attention (R14 version — best known). 128 q-rows per CTA,
// 4 q-groups x 2 kv-halves, 128-row KV chunks, ONE sync per chunk.
// K b-frags via ldmatrix.x4; exp via f16x2 MUFU interleaved with PV mma;
// l via hadd2-tree + quad shuffles. grid (NN/128, HEADS, BB), 256 threads.
// ===========================================================================
#define AKP 72   // K/V smem pitch (halves); 144B ≡ 16 mod 128

__global__ __launch_bounds__(256, 1) void attn_kernel()
{
    __shared__ __align__(16) char sbuf[73728];
    __half (*Ks)[128 * AKP] = reinterpret_cast<__half(*)[128 * AKP]>(sbuf);
    __half (*Vs)[128 * AKP] = reinterpret_cast<__half(*)[128 * AKP]>(sbuf + 36864);

    const int b  = blockIdx.z;
    const int h  = blockIdx.y;
    const int n0 = blockIdx.x * 128;
    const int tid = threadIdx.x;
    const int w   = tid >> 5, ln = tid & 31;
    const int gid = ln >> 2,  q  = ln & 3;
    const int qg  = w & 3;
    const int kh  = w >> 2;

    const int lmL   = ln & 7;
    const int lmSel = ln >> 3;
    const int lmRow = ((lmSel >> 1) << 3) + lmL;
    const int lmKof = (lmSel & 1) << 3;

    const __half2 LSC2 = __float2half2_rn(0.1803368801f);
    uint32_t qa[4][2][4];
    {
        const __half* Qg = g_Q + ((size_t)(b * NN + n0 + qg * 32)) * ADIM + h * DHEAD;
        #pragma unroll
        for (int kt = 0; kt < 4; kt++)
            #pragma unroll
            for (int mt = 0; mt < 2; mt++) {
                const __half* r0 = Qg + (size_t)(mt * 16 + gid) * ADIM + kt * 16 + 2 * q;
                const __half* r8 = r0 + 8 * ADIM;
                __half2 v0 = __hmul2(*reinterpret_cast<const __half2*>(r0),     LSC2);
                __half2 v1 = __hmul2(*reinterpret_cast<const __half2*>(r8),     LSC2);
                __half2 v2 = __hmul2(*reinterpret_cast<const __half2*>(r0 + 8), LSC2);
                __half2 v3 = __hmul2(*reinterpret_cast<const __half2*>(r8 + 8), LSC2);
                qa[kt][mt][0] = *reinterpret_cast<uint32_t*>(&v0);
                qa[kt][mt][1] = *reinterpret_cast<uint32_t*>(&v1);
                qa[kt][mt][2] = *reinterpret_cast<uint32_t*>(&v2);
                qa[kt][mt][3] = *reinterpret_cast<uint32_t*>(&v3);
            }
    }

    float oc[2][8][4] = {};
    float ls[2][2] = {};
    const __half* KVb = g_KV + (size_t)b * MM * KVC + h * DHEAD;

    auto load_chunk = [&](int m0, int bi) {
        #pragma unroll
        for (int u = 0; u < 8; u++) {
            int idx = u * 256 + tid;
            int tile = idx >> 10, r = (idx >> 3) & 127, f = idx & 7;
            const __half* src = KVb + (size_t)(m0 + r) * KVC + tile * ADIM + f * 8;
            __half* dst = (tile ? Vs[bi] : Ks[bi]) + r * AKP + f * 8;
            cpa16(dst, src);
        }
        CP_COMMIT();
    };

    load_chunk(0, 0);
    int buf = 0;

    for (int c = 0; c < MM / 128; c++) {
        CP_WAIT0();
        __syncthreads();
        if (c + 1 < MM / 128) load_chunk((c + 1) * 128, buf ^ 1);

        #pragma unroll
        for (int hh = 0; hh < 2; hh++) {
            const int base = hh * 64 + kh * 32;

            float sc[2][4][4] = {};
            #pragma unroll
            for (int kt = 0; kt < 4; kt++)
                #pragma unroll
                for (int pp = 0; pp < 2; pp++) {
                    uint32_t b00, b01, b10, b11;
                    ldmx4(b00, b01, b10, b11,
                          &Ks[buf][(base + pp * 16 + lmRow) * AKP + kt * 16 + lmKof]);
                    mma16(sc[0][2*pp],   qa[kt][0], b00, b01);
                    mma16(sc[1][2*pp],   qa[kt][1], b00, b01);
                    mma16(sc[0][2*pp+1], qa[kt][0], b10, b11);
                    mma16(sc[1][2*pp+1], qa[kt][1], b10, b11);
                }

            uint32_t sb[2][2][4];
            #pragma unroll
            for (int mt = 0; mt < 2; mt++)
                #pragma unroll
                for (int t = 0; t < 2; t++) {
                    sb[mt][t][0] = pack2(sc[mt][2*t][0],   sc[mt][2*t][1]);
                    sb[mt][t][1] = pack2(sc[mt][2*t][2],   sc[mt][2*t][3]);
                    sb[mt][t][2] = pack2(sc[mt][2*t+1][0], sc[mt][2*t+1][1]);
                    sb[mt][t][3] = pack2(sc[mt][2*t+1][2], sc[mt][2*t+1][3]);
                }

            uint32_t pa[2][2][4];
            #pragma unroll
            for (int i = 0; i < 4; i++) {
                pa[0][0][i] = hex2(sb[0][0][i]);
                pa[1][0][i] = hex2(sb[1][0][i]);
            }

            {
                int rowk = base + (ln & 15);
                #pragma unroll
                for (int nt = 0; nt < 8; nt++) {
                    uint32_t b0, b1;
                    ldmx2t(b0, b1, &Vs[buf][rowk * AKP + nt * 8]);
                    if (nt < 4) pa[0][1][nt] = hex2(sb[0][1][nt]);
                    mma16(oc[0][nt], pa[0][0], b0, b1);
                    if (nt >= 4) pa[1][1][nt - 4] = hex2(sb[1][1][nt - 4]);
                    mma16(oc[1][nt], pa[1][0], b0, b1);
                }
            }
            {
                int rowk = base + 16 + (ln & 15);
                #pragma unroll
                for (int nt = 0; nt < 8; nt++) {
                    uint32_t b0, b1;
                    ldmx2t(b0, b1, &Vs[buf][rowk * AKP + nt * 8]);
                    mma16(oc[0][nt], pa[0][1], b0, b1);
                    mma16(oc[1][nt], pa[1][1], b0, b1);
                }
            }

            #pragma unroll
            for (int mt = 0; mt < 2; mt++) {
                __half2 sA = __hadd2(__hadd2(u2h(pa[mt][0][0]), u2h(pa[mt][0][2])),
                                     __hadd2(u2h(pa[mt][1][0]), u2h(pa[mt][1][2])));
                float fA = __low2float(sA) + __high2float(sA);
                fA += __shfl_xor_sync(0xffffffffu, fA, 1);
                fA += __shfl_xor_sync(0xffffffffu, fA, 2);
                ls[mt][0] += fA;
                __half2 sB = __hadd2(__hadd2(u2h(pa[mt][0][1]), u2h(pa[mt][0][3])),
                                     __hadd2(u2h(pa[mt][1][1]), u2h(pa[mt][1][3])));
                float fB = __low2float(sB) + __high2float(sB);
                fB += __shfl_xor_sync(0xffffffffu, fB, 1);
                fB += __shfl_xor_sync(0xffffffffu, fB, 2);
                ls[mt][1] += fB;
            }
        }
        buf ^= 1;
    }

    float* redO = reinterpret_cast<float*>(sbuf);
    float* redL = reinterpret_cast<float*>(sbuf + 32768);
    __syncthreads();
    if (kh == 1) {
        #pragma unroll
        for (int mt = 0; mt < 2; mt++) {
            int r0 = qg * 32 + mt * 16 + gid;
            #pragma unroll
            for (int nt = 0; nt < 8; nt++) {
                int cc = nt * 8 + 2 * q;
                redO[r0 * 64 + cc]           = oc[mt][nt][0];
                redO[r0 * 64 + cc + 1]       = oc[mt][nt][1];
                redO[(r0 + 8) * 64 + cc]     = oc[mt][nt][2];
                redO[(r0 + 8) * 64 + cc + 1] = oc[mt][nt][3];
            }
            if (q == 0) {
                redL[r0]     = ls[mt][0];
                redL[r0 + 8] = ls[mt][1];
            }
        }
    }
    __syncthreads();
    if (kh == 0) {
        #pragma unroll
        for (int mt = 0; mt < 2; mt++) {
            int r0 = qg * 32 + mt * 16 + gid;
            float inv0 = 1.f / (ls[mt][0] + redL[r0]);
            float inv8 = 1.f / (ls[mt][1] + redL[r0 + 8]);
            __half* Og0 = g_O + ((size_t)(b * NN + n0 + r0)) * ADIM + h * DHEAD;
            __half* Og8 = Og0 + 8 * ADIM;
            #pragma unroll
            for (int nt = 0; nt < 8; nt++) {
                int cc = nt * 8 + 2 * q;
                float s0 = (oc[mt][nt][0] + redO[r0 * 64 + cc])           * inv0;
                float s1 = (oc[mt][nt][1] + redO[r0 * 64 + cc + 1])       * inv0;
                float s2 = (oc[mt][nt][2] + redO[(r0 + 8) * 64 + cc])     * inv8;
                float s3 = (oc[mt][nt][3] + redO[(r0 + 8) * 64 + cc + 1]) * inv8;
                *reinterpret_cast<__half2*>(&Og0[cc]) = __floats2half2_rn(s0, s1);
                *reinterpret_cast<__half2*>(&Og8[cc]) = __floats2half2_rn(s2, s3);
            }
        }
    }
}

// ---------------------------------------------------------------------------
// Launch: cvt, kv, q, attn (4th = profiled slot), out
// ---------------------------------------------------------------------------
extern "C" void kernel_launch(void* const* d_in, const int* in_sizes, int n_in,
                              void* d_out, int out_size)
{
    const float* x       = (const float*)d_in[0];
    const float* context = (const float*)d_in[1];
    const float* Wq      = (const float*)d_in[2];
    const float* Wkv     = (const float*)d_in[3];
    const float* Wo      = (const float*)d_in[4];
    const float* bo      = (const float*)d_in[5];
    float* out           = (float*)d_out;

    (void)in_sizes; (void)n_in; (void)out_size;

    dim3 blk(256);
    cvt_kernel<<<9984, blk>>>(x, context, Wq, Wkv, Wo);
    kv_kernel <<<dim3(KVC / 128,  (BB * MM) / 128), blk>>>();
    q_kernel  <<<dim3(ADIM / 64,  (BB * NN) / 128), blk>>>();
    attn_kernel<<<dim3(NN / 128, HEADS, BB), blk>>>();
    out_kernel<<<dim3(QDIM / 64,  (BB * NN) / 128), blk>>>(bo, out);
}